// round 7
// baseline (speedup 1.0000x reference)
#include <cuda_runtime.h>

#define THR  0.05f
#define BETA 0.9181805491303656f
#define TSTEPS 25
#define BATCH  64

typedef unsigned long long ull;

// ---------------- persistent state (module device memory; no allocations) ----
#define N1 (BATCH*16*16*128)   // 2,097,152
#define N2 (BATCH*32*8*64)     // 1,048,576
#define N3 (BATCH*64*4*32)     //   524,288

__device__ float g_syn1[N1];
__device__ float g_mem1[2][N1];
__device__ float g_spk1[BATCH*16*8*64];
__device__ float g_syn2[N2];
__device__ float g_mem2[2][N2];
__device__ float g_spk2[BATCH*32*4*32];
__device__ float g_syn3[N3];
__device__ float g_mem3[2][N3];
__device__ float g_spk3[BATCH*64*2*16];
__device__ float g_mem4[BATCH*512];
__device__ float g_spk4[BATCH*512];
__device__ float g_mem5[BATCH*2];

// Channel-pair interleaved weights:
// row = (g*CH/2 + c0)*CT + ic, 20 floats: tap t -> (w[c0][t], w[c0+CH/2][t]), pad
__device__ __align__(16) float g_wd_1[4 * 8  * 17 * 20];   // 10,880
__device__ __align__(16) float g_wd_2[4 * 16 * 48 * 20];   // 61,440
__device__ __align__(16) float g_wd_3[4 * 32 * 96 * 20];   // 245,760

// ---------------- f32x2 packed-FMA helpers (sm_103a FFMA2) ------------------
__device__ __forceinline__ ull pack2(float lo, float hi) {
    ull r;
    asm("mov.b64 %0, {%1, %2};" : "=l"(r) : "f"(lo), "f"(hi));
    return r;
}
__device__ __forceinline__ void unpack2(float& lo, float& hi, ull v) {
    asm("mov.b64 {%0, %1}, %2;" : "=f"(lo), "=f"(hi) : "l"(v));
}
__device__ __forceinline__ void ffma2(ull& d, ull a, ull b) {
    // d = a*b + d packed f32x2; per-half bit-identical to fmaf
    asm("fma.rn.f32x2 %0, %1, %2, %0;" : "+l"(d) : "l"(a), "l"(b));
}

// ---------------- accurate activations (match XLA lowering) -----------------
__device__ __forceinline__ float sigf(float x) {
    return 0.5f + 0.5f * tanhf(0.5f * x);
}
__device__ __forceinline__ float tanh_acc(float x) {
    return tanhf(x);
}

// ---------------- weight repack: channel-pair interleave --------------------
template<int CH, int CT>
__device__ void repack_pairs(const float* __restrict__ w, float* __restrict__ out,
                             int i0, int stride) {
    constexpr int CHH = CH / 2;
    const int total = 4 * CHH * CT * 20;
    for (int i = i0; i < total; i += stride) {
        int row = i / 20, s = i - row * 20;
        int gc = row / CT, ic = row - gc * CT;
        int g = gc / CHH, c0 = gc - g * CHH;
        int tap = s >> 1, h = s & 1;
        out[i] = (tap < 9) ? w[((size_t)(g * CH + c0 + h * CHH) * CT + ic) * 9 + tap]
                           : 0.f;
    }
}

__global__ void repack_kernel(const float* __restrict__ w1,
                              const float* __restrict__ w2,
                              const float* __restrict__ w3) {
    int stride = gridDim.x * blockDim.x;
    int i0 = blockIdx.x * blockDim.x + threadIdx.x;
    repack_pairs<16, 17>(w1, g_wd_1, i0, stride);
    repack_pairs<32, 48>(w2, g_wd_2, i0, stride);
    repack_pairs<64, 96>(w3, g_wd_3, i0, stride);
}

// ---------------- fused SConvLSTM layer (clean FFMA2) -----------------------
// One block = (batch b, pooled row ph). Thread (pw, c0) computes the channel
// PAIR {c0, c0+CH/2} at pooled cell (ph, pw): raw rows {r0,r0+1}, cols {2pw,2pw+1}.
// Accumulators are f32x2 pairs over the two channels; weights arrive as
// interleaved pairs (LDG.128), patch values as duplicated pairs (LDS.128).
// No pack instructions in the inner loop.
template<int CIN, int CH, int H, int W>
__global__ void __launch_bounds__(512)
sconvlstm_kernel(const float* __restrict__ xin,    // (B,CIN,H,W)
                 const float* __restrict__ memin,  // (B,CH,H,W)  prev mem
                 float*       __restrict__ syn,    // (B,CH,H,W)  in-place
                 float*       __restrict__ memout, // (B,CH,H,W)  next mem
                 float*       __restrict__ spk,    // (B,CH,H/2,W/2)
                 const float* __restrict__ wgtd,   // pair layout (4*CH/2*CT, 20)
                 const float* __restrict__ bias)   // (4CH)
{
    constexpr int CT  = CIN + CH;
    constexpr int PH  = H / 2, PW = W / 2;
    constexpr int WP  = W + 2;                     // padded width (logical cols)
    constexpr int CHH = CH / 2;
    constexpr int NT  = PW * CHH;                  // 512
    extern __shared__ float s_in[];                // [CT][4][WP] duplicated (2 floats/val)

    const int ph = blockIdx.x % PH;
    const int b  = blockIdx.x / PH;
    const int r0 = 2 * ph;
    const int tid = threadIdx.y * PW + threadIdx.x;

    // ---- stage input tile (x ‖ mem), 4 rows (halo), each value stored (v,v) -
    constexpr int TILE = CT * 4 * WP;
    for (int i = tid; i < TILE; i += NT) {
        int ch  = i / (4 * WP);
        int rem = i - ch * (4 * WP);
        int rr  = rem / WP;
        int cc  = rem - rr * WP;
        int r = r0 - 1 + rr;
        int c = cc - 1;
        float v = 0.f;
        if ((unsigned)r < (unsigned)H && (unsigned)c < (unsigned)W) {
            v = (ch < CIN) ? xin  [((b * CIN + ch)        * H + r) * W + c]
                           : memin[((b * CH  + (ch - CIN)) * H + r) * W + c];
        }
        *reinterpret_cast<float2*>(s_in + 2 * i) = make_float2(v, v);
    }
    __syncthreads();

    const int pw = threadIdx.x;      // pooled column
    const int c0 = threadIdx.y;      // channel-pair index

    ull acc[4][4];                   // [gate][pos: (r0,c), (r0,c+1), (r0+1,c), (r0+1,c+1)]
    #pragma unroll
    for (int g = 0; g < 4; g++) {
        float b0 = __ldg(bias + g * CH + c0);
        float b1 = __ldg(bias + g * CH + c0 + CHH);
        ull bp = pack2(b0, b1);
        acc[g][0] = bp; acc[g][1] = bp; acc[g][2] = bp; acc[g][3] = bp;
    }

    for (int ic = 0; ic < CT; ic++) {
        // patch pairs: padded cols 2pw .. 2pw+3 (raw 2pw-1 .. 2pw+2), duplicated
        ull pp[4][4];
        #pragma unroll
        for (int rr = 0; rr < 4; rr++) {
            const ulonglong2* q = reinterpret_cast<const ulonglong2*>(
                s_in + 2 * ((ic * 4 + rr) * WP + 2 * pw));       // 16B-aligned
            ulonglong2 q0 = q[0];
            ulonglong2 q1 = q[1];
            pp[rr][0] = q0.x; pp[rr][1] = q0.y;
            pp[rr][2] = q1.x; pp[rr][3] = q1.y;
        }
        #pragma unroll
        for (int g = 0; g < 4; g++) {
            const float* wrow = wgtd + ((size_t)(g * CHH + c0) * CT + ic) * 20;
            const ulonglong2* wq = reinterpret_cast<const ulonglong2*>(wrow);
            ulonglong2 a0 = __ldg(wq);
            ulonglong2 a1 = __ldg(wq + 1);
            ulonglong2 a2 = __ldg(wq + 2);
            ulonglong2 a3 = __ldg(wq + 3);
            ull w8 = __ldg(reinterpret_cast<const ull*>(wrow) + 8);
            ull wt[9] = {a0.x, a0.y, a1.x, a1.y, a2.x, a2.y, a3.x, a3.y, w8};
            #pragma unroll
            for (int kh = 0; kh < 3; kh++) {
                #pragma unroll
                for (int kw = 0; kw < 3; kw++) {
                    ull wv = wt[kh * 3 + kw];
                    ffma2(acc[g][0], wv, pp[kh    ][kw    ]);
                    ffma2(acc[g][1], wv, pp[kh    ][kw + 1]);
                    ffma2(acc[g][2], wv, pp[kh + 1][kw    ]);
                    ffma2(acc[g][3], wv, pp[kh + 1][kw + 1]);
                }
            }
        }
    }

    // ---- gate math + recurrence + maxpool + spike ---------------------------
    float av[4][4][2];               // [gate][pos][half]
    #pragma unroll
    for (int g = 0; g < 4; g++)
        #pragma unroll
        for (int p = 0; p < 4; p++)
            unpack2(av[g][p][0], av[g][p][1], acc[g][p]);

    #pragma unroll
    for (int u = 0; u < 2; u++) {
        const int c = c0 + u * CHH;
        float mx = -1e30f;
        #pragma unroll
        for (int pr = 0; pr < 2; pr++) {
            const int idx = ((b * CH + c) * H + (r0 + pr)) * W + 2 * pw;  // 8B-aligned
            float2 sv2 = *reinterpret_cast<const float2*>(syn + idx);
            float sv[2] = {sv2.x, sv2.y};
            float mv[2];
            #pragma unroll
            for (int pc = 0; pc < 2; pc++) {
                const int p = pr * 2 + pc;
                float gi = sigf(av[0][p][u]);
                float gf = sigf(av[1][p][u]);
                float gg = tanh_acc(av[2][p][u]);
                float go = sigf(av[3][p][u]);
                float s = gf * sv[pc] + gi * gg;
                sv[pc] = s;
                float m = go * tanh_acc(s);
                mv[pc] = m;
                mx = fmaxf(mx, m);
            }
            *reinterpret_cast<float2*>(syn    + idx) = make_float2(sv[0], sv[1]);
            *reinterpret_cast<float2*>(memout + idx) = make_float2(mv[0], mv[1]);
        }
        spk[((b * CH + c) * PH + ph) * PW + pw] = (mx > THR) ? 1.f : 0.f;
    }
}

// ---------------- FC1 (64x512x2048 GEMM) + Leaky, fused epilogue ------------
__global__ void __launch_bounds__(256)
fc1_leaky_kernel(const float* __restrict__ spk3,  // (64, 2048)
                 const float* __restrict__ w,     // (512, 2048)
                 const float* __restrict__ bias,  // (512)
                 float*       __restrict__ mem4,  // (64, 512) in-place
                 float*       __restrict__ spk4)  // (64, 512)
{
    __shared__ float As[32][33];
    __shared__ float Bs[16][33];
    const int tid   = threadIdx.x;
    const int mbase = (blockIdx.x & 1) * 32;
    const int nbase = (blockIdx.x >> 1) * 16;
    const int n  = tid & 15;
    const int mg = tid >> 4;
    float acc0 = 0.f, acc1 = 0.f;

    for (int kk = 0; kk < 2048; kk += 32) {
        for (int e = tid; e < 1024; e += 256) {
            int row = e >> 5, k = e & 31;
            As[row][k] = spk3[(mbase + row) * 2048 + kk + k];
        }
        for (int e = tid; e < 512; e += 256) {
            int row = e >> 5, k = e & 31;
            Bs[row][k] = w[(size_t)(nbase + row) * 2048 + kk + k];
        }
        __syncthreads();
        #pragma unroll
        for (int k = 0; k < 32; k++) {
            float bv = Bs[n][k];
            acc0 = fmaf(As[mg * 2][k],     bv, acc0);
            acc1 = fmaf(As[mg * 2 + 1][k], bv, acc1);
        }
        __syncthreads();
    }

    const int ncol = nbase + n;
    const float bv = bias[ncol];
    #pragma unroll
    for (int i = 0; i < 2; i++) {
        int m = mbase + mg * 2 + i;
        float cur = (i == 0 ? acc0 : acc1) + bv;
        int idx = m * 512 + ncol;
        float mo = mem4[idx];
        float reset = (mo > THR) ? THR : 0.f;       // reset from PREVIOUS mem
        float mn = BETA * mo + cur - reset;
        mem4[idx] = mn;
        spk4[idx] = ((mn - THR) > 0.f) ? 1.f : 0.f;
    }
}

// ---------------- FC2 + Leaky + output write --------------------------------
__global__ void fc2_leaky_out_kernel(const float* __restrict__ spk4,  // (64,512)
                                     const float* __restrict__ w,     // (2,512)
                                     const float* __restrict__ bias,  // (2)
                                     float*       __restrict__ mem5,  // (64,2)
                                     float*       __restrict__ out,   // [spk(25,64,2); mem(25,64,2)]
                                     int t)
{
    int tid = threadIdx.x;           // 128 threads = 64 b x 2 o
    int b = tid >> 1, o = tid & 1;
    const float* sr = spk4 + b * 512;
    const float* wr = w + o * 512;
    float s0 = 0.f, s1 = 0.f, s2 = 0.f, s3 = 0.f;
    #pragma unroll 4
    for (int k = 0; k < 512; k += 4) {
        s0 = fmaf(sr[k],     wr[k],     s0);
        s1 = fmaf(sr[k + 1], wr[k + 1], s1);
        s2 = fmaf(sr[k + 2], wr[k + 2], s2);
        s3 = fmaf(sr[k + 3], wr[k + 3], s3);
    }
    float acc = bias[o] + ((s0 + s1) + (s2 + s3));
    float mo = mem5[tid];
    float reset = (mo > THR) ? THR : 0.f;
    float mn = BETA * mo + acc - reset;
    mem5[tid] = mn;
    int oidx = (t * BATCH + b) * 2 + o;
    out[oidx] = ((mn - THR) > 0.f) ? 1.f : 0.f;        // spk_rec
    out[TSTEPS * BATCH * 2 + oidx] = mn;               // mem_rec
}

// ---------------- state zero-init (carry = zeros every call) ----------------
__global__ void zero_state_kernel() {
    int i = blockIdx.x * blockDim.x + threadIdx.x;
    int stride = gridDim.x * blockDim.x;
    for (int j = i; j < N1; j += stride) { g_syn1[j] = 0.f; g_mem1[0][j] = 0.f; }
    for (int j = i; j < N2; j += stride) { g_syn2[j] = 0.f; g_mem2[0][j] = 0.f; }
    for (int j = i; j < N3; j += stride) { g_syn3[j] = 0.f; g_mem3[0][j] = 0.f; }
    for (int j = i; j < BATCH * 512; j += stride) g_mem4[j] = 0.f;
    for (int j = i; j < BATCH * 2;   j += stride) g_mem5[j] = 0.f;
}

// ---------------- host launcher ---------------------------------------------
extern "C" void kernel_launch(void* const* d_in, const int* in_sizes, int n_in,
                              void* d_out, int out_size) {
    const float* x    = (const float*)d_in[0];
    const float* w1   = (const float*)d_in[1];
    const float* b1   = (const float*)d_in[2];
    const float* w2   = (const float*)d_in[3];
    const float* b2   = (const float*)d_in[4];
    const float* w3   = (const float*)d_in[5];
    const float* b3   = (const float*)d_in[6];
    const float* fc1w = (const float*)d_in[7];
    const float* fc1b = (const float*)d_in[8];
    const float* fc2w = (const float*)d_in[9];
    const float* fc2b = (const float*)d_in[10];
    float* out = (float*)d_out;

    float *p_syn1, *p_mem1, *p_spk1;
    float *p_syn2, *p_mem2, *p_spk2;
    float *p_syn3, *p_mem3, *p_spk3;
    float *p_mem4, *p_spk4, *p_mem5;
    float *p_wd1, *p_wd2, *p_wd3;
    cudaGetSymbolAddress((void**)&p_syn1, g_syn1);
    cudaGetSymbolAddress((void**)&p_mem1, g_mem1);
    cudaGetSymbolAddress((void**)&p_spk1, g_spk1);
    cudaGetSymbolAddress((void**)&p_syn2, g_syn2);
    cudaGetSymbolAddress((void**)&p_mem2, g_mem2);
    cudaGetSymbolAddress((void**)&p_spk2, g_spk2);
    cudaGetSymbolAddress((void**)&p_syn3, g_syn3);
    cudaGetSymbolAddress((void**)&p_mem3, g_mem3);
    cudaGetSymbolAddress((void**)&p_spk3, g_spk3);
    cudaGetSymbolAddress((void**)&p_mem4, g_mem4);
    cudaGetSymbolAddress((void**)&p_spk4, g_spk4);
    cudaGetSymbolAddress((void**)&p_mem5, g_mem5);
    cudaGetSymbolAddress((void**)&p_wd1, g_wd_1);
    cudaGetSymbolAddress((void**)&p_wd2, g_wd_2);
    cudaGetSymbolAddress((void**)&p_wd3, g_wd_3);

    constexpr int SM1 = 17 * 4 * 130 * 2 * 4;  //  70,720 B
    constexpr int SM2 = 48 * 4 * 66  * 2 * 4;  // 101,376 B
    constexpr int SM3 = 96 * 4 * 34  * 2 * 4;  // 104,448 B
    cudaFuncSetAttribute(sconvlstm_kernel<1, 16, 16, 128>,
                         cudaFuncAttributeMaxDynamicSharedMemorySize, SM1);
    cudaFuncSetAttribute(sconvlstm_kernel<16, 32, 8, 64>,
                         cudaFuncAttributeMaxDynamicSharedMemorySize, SM2);
    cudaFuncSetAttribute(sconvlstm_kernel<32, 64, 4, 32>,
                         cudaFuncAttributeMaxDynamicSharedMemorySize, SM3);

    zero_state_kernel<<<512, 256>>>();
    repack_kernel<<<256, 256>>>(w1, w2, w3);

    for (int t = 0; t < TSTEPS; t++) {
        int p = t & 1;
        sconvlstm_kernel<1, 16, 16, 128><<<BATCH * 8, dim3(64, 8), SM1>>>(
            x + (size_t)t * BATCH * 16 * 128,
            p_mem1 + p * N1, p_syn1, p_mem1 + (1 - p) * N1, p_spk1, p_wd1, b1);
        sconvlstm_kernel<16, 32, 8, 64><<<BATCH * 4, dim3(32, 16), SM2>>>(
            p_spk1, p_mem2 + p * N2, p_syn2, p_mem2 + (1 - p) * N2, p_spk2, p_wd2, b2);
        sconvlstm_kernel<32, 64, 4, 32><<<BATCH * 2, dim3(16, 32), SM3>>>(
            p_spk2, p_mem3 + p * N3, p_syn3, p_mem3 + (1 - p) * N3, p_spk3, p_wd3, b3);
        fc1_leaky_kernel<<<64, 256>>>(p_spk3, fc1w, fc1b, p_mem4, p_spk4);
        fc2_leaky_out_kernel<<<1, 128>>>(p_spk4, fc2w, fc2b, p_mem5, out, t);
    }
}

// round 8
// speedup vs baseline: 1.4146x; 1.4146x over previous
#include <cuda_runtime.h>

#define THR  0.05f
#define BETA 0.9181805491303656f
#define TSTEPS 25
#define BATCH  64

// ---------------- persistent state (module device memory; no allocations) ----
#define N1 (BATCH*16*16*128)   // 2,097,152
#define N2 (BATCH*32*8*64)     // 1,048,576
#define N3 (BATCH*64*4*32)     //   524,288

__device__ float g_syn1[N1];
__device__ float g_mem1[2][N1];
__device__ float g_spk1[2][BATCH*16*8*64];
__device__ float g_syn2[N2];
__device__ float g_mem2[2][N2];
__device__ float g_spk2[2][BATCH*32*4*32];
__device__ float g_syn3[N3];
__device__ float g_mem3[2][N3];
__device__ float g_spk3[2][BATCH*64*2*16];
__device__ float g_mem4[BATCH*512];
__device__ float g_spk4[2][BATCH*512];
__device__ float g_mem5[BATCH*2];

// Repacked weights: [gch][ic][12] (taps 0..8, pad 9..11 = 0), 16B-aligned rows
__device__ __align__(16) float g_wp_1[64  * 17 * 12];
__device__ __align__(16) float g_wp_2[128 * 48 * 12];
__device__ __align__(16) float g_wp_3[256 * 96 * 12];

// ---------------- accurate activations (match XLA lowering) -----------------
__device__ __forceinline__ float sigf(float x) {
    return 0.5f + 0.5f * tanhf(0.5f * x);
}
__device__ __forceinline__ float tanh_acc(float x) {
    return tanhf(x);
}

// ---------------- weight repack: (rows, 9) -> (rows, 12) padded -------------
__global__ void repack_kernel(const float* __restrict__ w1,
                              const float* __restrict__ w2,
                              const float* __restrict__ w3) {
    const int r1 = 64 * 17, r2 = 128 * 48, r3 = 256 * 96;
    int stride = gridDim.x * blockDim.x;
    int i0 = blockIdx.x * blockDim.x + threadIdx.x;
    for (int i = i0; i < r1 * 12; i += stride) {
        int row = i / 12, s = i - row * 12;
        g_wp_1[i] = (s < 9) ? w1[row * 9 + s] : 0.f;
    }
    for (int i = i0; i < r2 * 12; i += stride) {
        int row = i / 12, s = i - row * 12;
        g_wp_2[i] = (s < 9) ? w2[row * 9 + s] : 0.f;
    }
    for (int i = i0; i < r3 * 12; i += stride) {
        int row = i / 12, s = i - row * 12;
        g_wp_3[i] = (s < 9) ? w3[row * 9 + s] : 0.f;
    }
}

// ---------------- fused SConvLSTM layer body (R6-exact math) ----------------
// bid = (batch b, pooled row ph). Thread (pwp, c): channel c, raw rows
// {r0, r0+1}, raw cols {w0..w0+3}. conv gates -> syn/mem -> maxpool -> spikes.
template<int CIN, int CH, int H, int W>
__device__ __forceinline__ void conv_layer(
    int bid,
    const float* __restrict__ xin,    // (B,CIN,H,W)
    const float* __restrict__ memin,  // (B,CH,H,W)  prev mem
    float*       __restrict__ syn,    // (B,CH,H,W)  in-place
    float*       __restrict__ memout, // (B,CH,H,W)  next mem
    float*       __restrict__ spk,    // (B,CH,H/2,W/2)
    const float* __restrict__ wgt,    // repacked (4CH*CT, 12)
    const float* __restrict__ bias,   // (4CH)
    float*       __restrict__ s_in)   // shared [CT][4][WP]
{
    constexpr int CT  = CIN + CH;
    constexpr int PH  = H / 2, PW = W / 2;
    constexpr int WP  = W + 4;                     // row stride: 16B multiple
    constexpr int NT  = (PW / 2) * CH;             // 512

    const int ph = bid % PH;
    const int b  = bid / PH;
    const int r0 = 2 * ph;
    const int tid = threadIdx.x;

    // ---- stage input tile (x ‖ mem), 4 rows (halo), zero-padded cols -------
    constexpr int TILE = CT * 4 * WP;
    for (int i = tid; i < TILE; i += NT) {
        int ch  = i / (4 * WP);
        int rem = i - ch * (4 * WP);
        int rr  = rem / WP;
        int cc  = rem - rr * WP;
        int r = r0 - 1 + rr;
        int c = cc - 1;
        float v = 0.f;
        if ((unsigned)r < (unsigned)H && (unsigned)c < (unsigned)W) {
            v = (ch < CIN) ? xin  [((b * CIN + ch)        * H + r) * W + c]
                           : memin[((b * CH  + (ch - CIN)) * H + r) * W + c];
        }
        s_in[i] = v;
    }
    __syncthreads();

    const int pwp = tid % (PW / 2);  // pooled-column pair index
    const int c   = tid / (PW / 2);  // hidden channel
    const int w0  = 4 * pwp;         // first raw column (16B-aligned smem idx)

    float acc[4][8];                 // [gate][pr*4 + j]
    #pragma unroll
    for (int g = 0; g < 4; g++) {
        float bv = __ldg(bias + g * CH + c);
        #pragma unroll
        for (int p = 0; p < 8; p++) acc[g][p] = bv;
    }

    for (int ic = 0; ic < CT; ic++) {
        const float* sp = s_in + ic * (4 * WP) + w0;
        float patch[4][6];           // raw cols w0-1 .. w0+4 (smem idx w0..w0+5)
        #pragma unroll
        for (int rr = 0; rr < 4; rr++) {
            float4 q = *reinterpret_cast<const float4*>(sp + rr * WP);
            float2 d = *reinterpret_cast<const float2*>(sp + rr * WP + 4);
            patch[rr][0] = q.x; patch[rr][1] = q.y; patch[rr][2] = q.z;
            patch[rr][3] = q.w; patch[rr][4] = d.x; patch[rr][5] = d.y;
        }
        #pragma unroll
        for (int g = 0; g < 4; g++) {
            const float4* wq = reinterpret_cast<const float4*>(
                wgt + ((size_t)(g * CH + c) * CT + ic) * 12);
            float4 qa = __ldg(wq);
            float4 qb = __ldg(wq + 1);
            float4 qc = __ldg(wq + 2);
            float wt[9] = {qa.x, qa.y, qa.z, qa.w, qb.x, qb.y, qb.z, qb.w, qc.x};
            #pragma unroll
            for (int kh = 0; kh < 3; kh++) {
                #pragma unroll
                for (int kw = 0; kw < 3; kw++) {
                    float wv = wt[kh * 3 + kw];
                    #pragma unroll
                    for (int j = 0; j < 4; j++) {
                        acc[g][j]     = fmaf(wv, patch[kh    ][j + kw], acc[g][j]);
                        acc[g][4 + j] = fmaf(wv, patch[kh + 1][j + kw], acc[g][4 + j]);
                    }
                }
            }
        }
    }

    // ---- gate math + recurrence + maxpool + spike ---------------------------
    float mx0 = -1e30f, mx1 = -1e30f;
    #pragma unroll
    for (int pr = 0; pr < 2; pr++) {
        const int rowidx = ((b * CH + c) * H + (r0 + pr)) * W + w0;   // 16B-aligned
        float4 sv4 = *reinterpret_cast<const float4*>(syn + rowidx);
        float sv[4] = {sv4.x, sv4.y, sv4.z, sv4.w};
        float mv[4];
        #pragma unroll
        for (int j = 0; j < 4; j++) {
            const int p = pr * 4 + j;
            float gi = sigf(acc[0][p]);
            float gf = sigf(acc[1][p]);
            float gg = tanh_acc(acc[2][p]);
            float go = sigf(acc[3][p]);
            float s = gf * sv[j] + gi * gg;
            sv[j] = s;
            float m = go * tanh_acc(s);
            mv[j] = m;
            if (j < 2) mx0 = fmaxf(mx0, m); else mx1 = fmaxf(mx1, m);
        }
        *reinterpret_cast<float4*>(syn    + rowidx) = make_float4(sv[0], sv[1], sv[2], sv[3]);
        *reinterpret_cast<float4*>(memout + rowidx) = make_float4(mv[0], mv[1], mv[2], mv[3]);
    }
    const int spkidx = ((b * CH + c) * PH + ph) * PW + 2 * pwp;
    spk[spkidx]     = (mx0 > THR) ? 1.f : 0.f;
    spk[spkidx + 1] = (mx1 > THR) ? 1.f : 0.f;
}

// ---------------- FC1 body: 64 tiles of 32m x 16n, 512 thr, 1 output each ---
// Per-output K order (kk asc, k asc) identical to previous version -> bit-exact.
__device__ __forceinline__ void fc1_layer(
    int bid,
    const float* __restrict__ spk3,  // (64, 2048)
    const float* __restrict__ w,     // (512, 2048)
    const float* __restrict__ bias,  // (512)
    float*       __restrict__ mem4,  // (64, 512) in-place
    float*       __restrict__ spk4,  // (64, 512)
    float*       __restrict__ smem)  // >= (32+16)*33 floats
{
    float* As = smem;            // [32][33]
    float* Bs = smem + 32 * 33;  // [16][33]
    const int tid   = threadIdx.x;
    const int mbase = (bid & 1) * 32;
    const int nbase = (bid >> 1) * 16;
    const int n = tid & 15;
    const int m = tid >> 4;      // 0..31
    float acc = 0.f;

    for (int kk = 0; kk < 2048; kk += 32) {
        for (int e = tid; e < 1024; e += 512) {
            int row = e >> 5, k = e & 31;
            As[row * 33 + k] = spk3[(mbase + row) * 2048 + kk + k];
        }
        if (tid < 512) {
            int e = tid;
            int row = e >> 5, k = e & 31;
            Bs[row * 33 + k] = w[(size_t)(nbase + row) * 2048 + kk + k];
        }
        __syncthreads();
        #pragma unroll
        for (int k = 0; k < 32; k++)
            acc = fmaf(As[m * 33 + k], Bs[n * 33 + k], acc);
        __syncthreads();
    }

    const int ncol = nbase + n;
    float cur = acc + bias[ncol];
    int idx = (mbase + m) * 512 + ncol;
    float mo = mem4[idx];
    float reset = (mo > THR) ? THR : 0.f;           // reset from PREVIOUS mem
    float mn = BETA * mo + cur - reset;
    mem4[idx] = mn;
    spk4[idx] = ((mn - THR) > 0.f) ? 1.f : 0.f;
}

// ---------------- FC2 body ---------------------------------------------------
__device__ __forceinline__ void fc2_layer(
    const float* __restrict__ spk4,  // (64,512)
    const float* __restrict__ w,     // (2,512)
    const float* __restrict__ bias,  // (2)
    float*       __restrict__ mem5,  // (64,2)
    float*       __restrict__ out,   // [spk(25,64,2); mem(25,64,2)]
    int t)
{
    int tid = threadIdx.x;
    if (tid >= 128) return;          // no syncs below
    int b = tid >> 1, o = tid & 1;
    const float* sr = spk4 + b * 512;
    const float* wr = w + o * 512;
    float s0 = 0.f, s1 = 0.f, s2 = 0.f, s3 = 0.f;
    #pragma unroll 4
    for (int k = 0; k < 512; k += 4) {
        s0 = fmaf(sr[k],     wr[k],     s0);
        s1 = fmaf(sr[k + 1], wr[k + 1], s1);
        s2 = fmaf(sr[k + 2], wr[k + 2], s2);
        s3 = fmaf(sr[k + 3], wr[k + 3], s3);
    }
    float acc = bias[o] + ((s0 + s1) + (s2 + s3));
    float mo = mem5[tid];
    float reset = (mo > THR) ? THR : 0.f;
    float mn = BETA * mo + acc - reset;
    mem5[tid] = mn;
    int oidx = (t * BATCH + b) * 2 + o;
    out[oidx] = ((mn - THR) > 0.f) ? 1.f : 0.f;        // spk_rec
    out[TSTEPS * BATCH * 2 + oidx] = mn;               // mem_rec
}

// ---------------- pipelined super-kernel -------------------------------------
// Launch slot k runs concurrently: L3(k-2) | L2(k-1) | L1(k) | FC1(k-3) | FC2(k-4).
// All producers are in earlier launches; inter-stage spk buffers are parity-
// double-buffered (writer/reader of same parity always >= 2 launches apart).
// Longest blocks (L3) at lowest bid so they start first.
__global__ void __launch_bounds__(512)
pipeline_kernel(int k,
                const float* __restrict__ x,
                const float* __restrict__ b1,
                const float* __restrict__ b2,
                const float* __restrict__ b3,
                const float* __restrict__ fc1w, const float* __restrict__ fc1b,
                const float* __restrict__ fc2w, const float* __restrict__ fc2b,
                float* __restrict__ out)
{
    extern __shared__ float smem[];
    const int bid = blockIdx.x;

    if (bid < 128) {                               // ---- L3, t = k-2
        int t = k - 2;
        if ((unsigned)t >= TSTEPS) return;
        int p = t & 1;
        conv_layer<32, 64, 4, 32>(bid,
            g_spk2[p], g_mem3[p], g_syn3, g_mem3[1 - p], g_spk3[p],
            g_wp_3, b3, smem);
    } else if (bid < 384) {                        // ---- L2, t = k-1
        int t = k - 1;
        if ((unsigned)t >= TSTEPS) return;
        int p = t & 1;
        conv_layer<16, 32, 8, 64>(bid - 128,
            g_spk1[p], g_mem2[p], g_syn2, g_mem2[1 - p], g_spk2[p],
            g_wp_2, b2, smem);
    } else if (bid < 896) {                        // ---- L1, t = k
        int t = k;
        if ((unsigned)t >= TSTEPS) return;
        int p = t & 1;
        conv_layer<1, 16, 16, 128>(bid - 384,
            x + (size_t)t * BATCH * 16 * 128,
            g_mem1[p], g_syn1, g_mem1[1 - p], g_spk1[p],
            g_wp_1, b1, smem);
    } else if (bid < 960) {                        // ---- FC1, t = k-3
        int t = k - 3;
        if ((unsigned)t >= TSTEPS) return;
        int p = t & 1;
        fc1_layer(bid - 896, g_spk3[p], fc1w, fc1b, g_mem4, g_spk4[p], smem);
    } else {                                       // ---- FC2, t = k-4
        int t = k - 4;
        if ((unsigned)t >= TSTEPS) return;
        int p = t & 1;
        fc2_layer(g_spk4[p], fc2w, fc2b, g_mem5, out, t);
    }
}

// ---------------- state zero-init (carry = zeros every call) ----------------
__global__ void zero_state_kernel() {
    int i = blockIdx.x * blockDim.x + threadIdx.x;
    int stride = gridDim.x * blockDim.x;
    for (int j = i; j < N1; j += stride) { g_syn1[j] = 0.f; g_mem1[0][j] = 0.f; }
    for (int j = i; j < N2; j += stride) { g_syn2[j] = 0.f; g_mem2[0][j] = 0.f; }
    for (int j = i; j < N3; j += stride) { g_syn3[j] = 0.f; g_mem3[0][j] = 0.f; }
    for (int j = i; j < BATCH * 512; j += stride) g_mem4[j] = 0.f;
    for (int j = i; j < BATCH * 2;   j += stride) g_mem5[j] = 0.f;
}

// ---------------- host launcher ---------------------------------------------
extern "C" void kernel_launch(void* const* d_in, const int* in_sizes, int n_in,
                              void* d_out, int out_size) {
    const float* x    = (const float*)d_in[0];
    const float* w1   = (const float*)d_in[1];
    const float* b1   = (const float*)d_in[2];
    const float* w2   = (const float*)d_in[3];
    const float* b2   = (const float*)d_in[4];
    const float* w3   = (const float*)d_in[5];
    const float* b3   = (const float*)d_in[6];
    const float* fc1w = (const float*)d_in[7];
    const float* fc1b = (const float*)d_in[8];
    const float* fc2w = (const float*)d_in[9];
    const float* fc2b = (const float*)d_in[10];
    float* out = (float*)d_out;

    // max conv smem: L3 = 96*4*36*4 = 55,296 B (L1 35,904; L2 52,224; FC1 6,336)
    constexpr int SMEM = 96 * 4 * 36 * 4;
    cudaFuncSetAttribute(pipeline_kernel,
                         cudaFuncAttributeMaxDynamicSharedMemorySize, SMEM);

    zero_state_kernel<<<512, 256>>>();
    repack_kernel<<<256, 256>>>(w1, w2, w3);

    for (int k = 0; k < TSTEPS + 4; k++) {
        pipeline_kernel<<<961, 512, SMEM>>>(k, x, b1, b2, b3,
                                            fc1w, fc1b, fc2w, fc2b, out);
    }
}